// round 12
// baseline (speedup 1.0000x reference)
#include <cuda_runtime.h>

// Reference semantics: image (B,M,N,2) raw-reinterpreted as (2B,M,N) planes;
// flow2[p] = flow[p>>1]; out[p*MN + y*N + x] = bilinear(plane p, x+dx, y+dy),
// zero outside bounds.
// Mapping: block = 256 threads covering a 2-row strip (768 px) of one batch,
// ILP=3 pixels per thread (q = tid + i*256). y/x derived from q via a single
// compare+select (no div/mod); flow and out addresses are linear in q
// (fully coalesced). Lanes stay on consecutive x -> tight gather wavefronts.
// Occupancy: 32 regs, 256 thr -> 8 blocks/SM (100% theoretical).

#define MM 384
#define NN 384
#define MN (MM * NN)
#define ILP 3

__global__ __launch_bounds__(256) void warp_kernel(
    const float*  __restrict__ image,  // 2B*MN floats (raw)
    const float2* __restrict__ flow,   // B*MN float2
    float*        __restrict__ out)    // 2B*MN floats (raw)
{
    int bid = blockIdx.x;
    int b   = bid / 192;                 // uniform per block
    int y0  = (bid - b * 192) * 2;       // strip's first row
    int tid = threadIdx.x;

    const size_t pbase = (size_t)(2 * b) * MN;
    const float*  pA    = image + pbase;
    const float*  pB    = pA + MN;
    const float2* fbase = flow + (size_t)b * MN + y0 * NN;
    float*        oA    = out + pbase + (size_t)y0 * NN;

    // flow loads for 3 strip positions (independent, streaming, coalesced)
    int    q[ILP];
    float2 f[ILP];
#pragma unroll
    for (int i = 0; i < ILP; i++) {
        q[i] = tid + i * 256;            // 0..767 within strip
        f[i] = __ldcs(fbase + q[i]);
    }

    int   o00[ILP], o01[ILP], o10[ILP], o11[ILP];
    float w00[ILP], w01[ILP], w10[ILP], w11[ILP];

#pragma unroll
    for (int i = 0; i < ILP; i++) {
        int dy = (q[i] >= NN) ? 1 : 0;   // row within strip
        int x  = q[i] - (dy ? NN : 0);
        int y  = y0 + dy;

        float xs = (float)x + f[i].x;
        float ys = (float)y + f[i].y;

        float x0f = floorf(xs);
        float y0f = floorf(ys);
        float wx = xs - x0f;
        float wy = ys - y0f;
        int xi0 = (int)x0f;
        int yi0 = (int)y0f;
        int xi1 = xi0 + 1;
        int yi1 = yi0 + 1;

        float wxm0 = ((unsigned)xi0 < (unsigned)NN) ? (1.0f - wx) : 0.0f;
        float wxm1 = ((unsigned)xi1 < (unsigned)NN) ? wx : 0.0f;
        float wym0 = ((unsigned)yi0 < (unsigned)MM) ? (1.0f - wy) : 0.0f;
        float wym1 = ((unsigned)yi1 < (unsigned)MM) ? wy : 0.0f;

        int xc0 = min(max(xi0, 0), NN - 1);
        int xc1 = min(max(xi1, 0), NN - 1);
        int yc0 = min(max(yi0, 0), MM - 1);
        int yc1 = min(max(yi1, 0), MM - 1);

        o00[i] = yc0 * NN + xc0;
        o01[i] = yc0 * NN + xc1;
        o10[i] = yc1 * NN + xc0;
        o11[i] = yc1 * NN + xc1;
        w00[i] = wym0 * wxm0;
        w01[i] = wym0 * wxm1;
        w10[i] = wym1 * wxm0;
        w11[i] = wym1 * wxm1;
    }

    // front-batch all 24 gathers
    float vA00[ILP], vA01[ILP], vA10[ILP], vA11[ILP];
    float vB00[ILP], vB01[ILP], vB10[ILP], vB11[ILP];
#pragma unroll
    for (int i = 0; i < ILP; i++) {
        vA00[i] = __ldg(pA + o00[i]);
        vA01[i] = __ldg(pA + o01[i]);
        vA10[i] = __ldg(pA + o10[i]);
        vA11[i] = __ldg(pA + o11[i]);
        vB00[i] = __ldg(pB + o00[i]);
        vB01[i] = __ldg(pB + o01[i]);
        vB10[i] = __ldg(pB + o10[i]);
        vB11[i] = __ldg(pB + o11[i]);
    }

#pragma unroll
    for (int i = 0; i < ILP; i++) {
        float accA = vA00[i] * w00[i] + vA01[i] * w01[i]
                   + vA10[i] * w10[i] + vA11[i] * w11[i];
        float accB = vB00[i] * w00[i] + vB01[i] * w01[i]
                   + vB10[i] * w10[i] + vB11[i] * w11[i];
        __stcs(oA + q[i], accA);          // coalesced, linear in q
        __stcs(oA + MN + q[i], accB);
    }
}

extern "C" void kernel_launch(void* const* d_in, const int* in_sizes, int n_in,
                              void* d_out, int out_size)
{
    const float*  image = (const float*)d_in[0];
    const float2* flow  = (const float2*)d_in[1];
    float* out = (float*)d_out;

    int B = out_size / (2 * MN);
    int blocks = B * (MM / 2);    // 64 * 192 = 12288
    warp_kernel<<<blocks, 256>>>(image, flow, out);
}